// round 17
// baseline (speedup 1.0000x reference)
#include <cuda_runtime.h>
#include <cuda_fp16.h>
#include <math.h>
#include <stdint.h>

#define Tdim 2048
#define Ddim 256
#define CACT 64
#define CTIME 32
#define NROWS (8 * 2048)
#define LABEL_ID_ 3
#define CHUNK 32

// ---- gemm smem (byte offsets), block = 128 rows x 48 cols ----
#define B_HI 0                    // 48 x 132 u32 (packed fp16 k-pairs, hi only)
#define A_H0 25344                // 128 rows x 128B (fp16 hi, one K-quarter)
#define A_L0 41728                // 128 rows x 128B (fp16 lo)
// ---- proto smem (float offsets) ----
#define P_Q   0                   // 32 x 260
#define P_HN  8320                // 32 x 260
#define P_G   16640               // 32 x 32
#define P_M   17664               // 32 x 32
#define P_SB  18688               // 32 x 32 (num)
#define P_N2  19712               // 32 x 32 (sims out)
#define P_TOK 20736               // 2048 ints
#define SMEM_BYTES 91136

__device__ float g_scr[(long)NROWS * 96];
__device__ int   g_evt[24 * Tdim];
__device__ int   g_evn[24 * Tdim];
__device__ int   g_done[8];

__device__ __forceinline__ float softplusf(float x) { return log1pf(expf(x)); }

__device__ __forceinline__ uint32_t smem_u32(const void* p) {
    uint32_t a;
    asm("{ .reg .u64 t; cvta.to.shared.u64 t, %1; cvt.u32.u64 %0, t; }" : "=r"(a) : "l"(p));
    return a;
}
// fp16 exact split: x = hi + lo with hi = fp16(x), lo = fp16(x - hi)
__device__ __forceinline__ void hilo16(float x0, float x1, uint32_t& hi, uint32_t& lo) {
    __half2 h = __floats2half2_rn(x0, x1);
    float2 bk = __half22float2(h);
    __half2 l = __floats2half2_rn(x0 - bk.x, x1 - bk.y);
    hi = *(uint32_t*)&h;
    lo = *(uint32_t*)&l;
}
__device__ __forceinline__ uint32_t h16hi(float x0, float x1) {
    __half2 h = __floats2half2_rn(x0, x1);
    return *(uint32_t*)&h;
}
__device__ __forceinline__ void ldsm4(uint32_t addr, uint32_t& r0, uint32_t& r1,
                                      uint32_t& r2, uint32_t& r3) {
    asm volatile("ldmatrix.sync.aligned.m8n8.x4.shared.b16 {%0,%1,%2,%3}, [%4];"
                 : "=r"(r0), "=r"(r1), "=r"(r2), "=r"(r3) : "r"(addr));
}
__device__ __forceinline__ void mmaf16(float* c, uint32_t a0, uint32_t a1,
                                       uint32_t a2, uint32_t a3,
                                       uint32_t b0, uint32_t b1) {
    asm volatile(
        "mma.sync.aligned.m16n8k16.row.col.f32.f16.f16.f32 "
        "{%0,%1,%2,%3},{%4,%5,%6,%7},{%8,%9},{%0,%1,%2,%3};"
        : "+f"(c[0]), "+f"(c[1]), "+f"(c[2]), "+f"(c[3])
        : "r"(a0), "r"(a1), "r"(a2), "r"(a3), "r"(b0), "r"(b1));
}

__global__ void reset_kernel() {
    if (threadIdx.x < 8) g_done[threadIdx.x] = 0;
}

__global__ void __launch_bounds__(256, 2) fat_kernel(
    const int* __restrict__ tokens, const float* __restrict__ h,
    const float* __restrict__ E,
    const float* __restrict__ Wn, const float* __restrict__ bn,
    const float* __restrict__ Wt, const float* __restrict__ bt,
    const float* __restrict__ tsa, const float* __restrict__ tst,
    const float* __restrict__ psa, const float* __restrict__ pst,
    const float* __restrict__ ppa, const float* __restrict__ ppt,
    const float* __restrict__ pta, const float* __restrict__ ptt,
    float* __restrict__ out)
{
    extern __shared__ char smc[];
    float* sm = (float*)smc;
    int tid = threadIdx.x, lane = tid & 31, wid = tid >> 5;
    int bx = blockIdx.x;

    if (bx >= 24) {
        // ============ GEMM role: fp16 A-exact / B-hi, 2-pass, 4x2 warp tiles ============
        __shared__ float s_bias[48];

        int g = bx - 24;
        int half = g & 1;
        long rowbase = (long)(g >> 1) * 128;
        int b = (int)(rowbase >> 11);
        float s_ta = softplusf(*tsa), s_tt = softplusf(*tst);

        if (tid < 48) {
            int c = half * 48 + tid;
            s_bias[tid] = (c < CACT) ? bn[c] : bt[c - CACT];
        }

        uint32_t* BH32 = (uint32_t*)(smc + B_HI);
        const float4* gh4 = (const float4*)h;

        // prologue: prefetch A quarter 0 first (DRAM latency overlaps B fold)
        float4 pv0[4], pv1[4];
#pragma unroll
        for (int it = 0; it < 4; ++it) {
            int i = tid + 256 * it;
            int r = i >> 3, c = i & 7;
            pv0[it] = gh4[(rowbase + r) * 64 + 2 * c];
            pv1[it] = gh4[(rowbase + r) * 64 + 2 * c + 1];
        }

        // ---- fold B half: 48 cols x 128 k-pairs, fp16 hi only ----
        {
            const float2* E2 = (const float2*)E;
#pragma unroll
            for (int it = 0; it < 24; ++it) {
                int i = tid + 256 * it;
                int c = i >> 7, kp = i & 127;
                int cg = half * 48 + c;
                const float2* wrow = (cg < CACT) ? (const float2*)(Wn + cg * Ddim)
                                                 : (const float2*)(Wt + (cg - CACT) * Ddim);
                int erow = (cg < CACT) ? (4 + cg) : (68 + (cg - CACT));
                float sc = (cg < CACT) ? s_ta : s_tt;
                float2 wv = wrow[kp];
                float2 ev = E2[erow * 128 + kp];
                BH32[c * 132 + kp] = h16hi(fmaf(sc, ev.x, wv.x), fmaf(sc, ev.y, wv.y));
            }
        }

        float accH[2][3][4], accL[2][3][4];
#pragma unroll
        for (int rt = 0; rt < 2; ++rt)
#pragma unroll
            for (int j = 0; j < 3; ++j)
#pragma unroll
                for (int i = 0; i < 4; ++i) { accH[rt][j][i] = 0.f; accL[rt][j][i] = 0.f; }

        uint32_t smem_base = smem_u32(smc);
        int rt2 = wid >> 1;                 // 0..3: rows [32*rt2, 32*rt2+32)
        int ch2 = wid & 1;                  // 0..1: cols [24*ch2, 24*ch2+24)
        int a_row0 = rt2 * 32 + (lane & 15);
        int a_row1 = a_row0 + 16;
        int a_half = lane >> 4;

        for (int q = 0; q < 4; ++q) {
            __syncthreads();   // previous quarter's A reads complete
#pragma unroll
            for (int it = 0; it < 4; ++it) {
                int i = tid + 256 * it;
                int r = i >> 3, c = i & 7;
                uint4 hi4, lo4;
                hilo16(pv0[it].x, pv0[it].y, hi4.x, lo4.x);
                hilo16(pv0[it].z, pv0[it].w, hi4.y, lo4.y);
                hilo16(pv1[it].x, pv1[it].y, hi4.z, lo4.z);
                hilo16(pv1[it].z, pv1[it].w, hi4.w, lo4.w);
                int sw = (c ^ (r & 7)) * 16;
                *(uint4*)(smc + A_H0 + r * 128 + sw) = hi4;
                *(uint4*)(smc + A_L0 + r * 128 + sw) = lo4;
            }
            if (q < 3) {
#pragma unroll
                for (int it = 0; it < 4; ++it) {
                    int i = tid + 256 * it;
                    int r = i >> 3, c = i & 7;
                    pv0[it] = gh4[(rowbase + r) * 64 + (q + 1) * 16 + 2 * c];
                    pv1[it] = gh4[(rowbase + r) * 64 + (q + 1) * 16 + 2 * c + 1];
                }
            }
            __syncthreads();   // staging visible

#pragma unroll
            for (int kc = 0; kc < 4; ++kc) {
                int chunk = kc * 2 + a_half;
                uint32_t off0 = a_row0 * 128 + ((chunk ^ (a_row0 & 7)) * 16);
                uint32_t off1 = a_row1 * 128 + ((chunk ^ (a_row1 & 7)) * 16);
                uint32_t h00, h01, h02, h03, h10, h11, h12, h13;
                uint32_t l00, l01, l02, l03, l10, l11, l12, l13;
                ldsm4(smem_base + A_H0 + off0, h00, h01, h02, h03);
                ldsm4(smem_base + A_H0 + off1, h10, h11, h12, h13);
                ldsm4(smem_base + A_L0 + off0, l00, l01, l02, l03);
                ldsm4(smem_base + A_L0 + off1, l10, l11, l12, l13);

                int kpb = (q * 4 + kc) * 8;
#pragma unroll
                for (int j = 0; j < 3; ++j) {
                    int idx0 = (ch2 * 24 + j * 8 + (lane >> 2)) * 132 + kpb + (lane & 3);
                    uint32_t bh0 = BH32[idx0], bh1 = BH32[idx0 + 4];
                    mmaf16(accH[0][j], h00, h01, h02, h03, bh0, bh1);
                    mmaf16(accL[0][j], l00, l01, l02, l03, bh0, bh1);
                    mmaf16(accH[1][j], h10, h11, h12, h13, bh0, bh1);
                    mmaf16(accL[1][j], l10, l11, l12, l13, bh0, bh1);
                }
            }
        }

        // ---- epilogue: combine H+L, stage 128 x 48 to ob, direct stores ----
        __syncthreads();
        float* ob = sm;
        {
            int r0 = rt2 * 32 + (lane >> 2);
            int cb = ch2 * 24 + 2 * (lane & 3);
#pragma unroll
            for (int rt = 0; rt < 2; ++rt) {
                int rr = r0 + rt * 16;
#pragma unroll
                for (int j = 0; j < 3; ++j) {
                    int col = cb + 8 * j;
                    ob[rr * 52 + col]           = accH[rt][j][0] + accL[rt][j][0] + s_bias[col];
                    ob[rr * 52 + col + 1]       = accH[rt][j][1] + accL[rt][j][1] + s_bias[col + 1];
                    ob[(rr + 8) * 52 + col]     = accH[rt][j][2] + accL[rt][j][2] + s_bias[col];
                    ob[(rr + 8) * 52 + col + 1] = accH[rt][j][3] + accL[rt][j][3] + s_bias[col + 1];
                }
            }
        }
        __syncthreads();

        if (half == 0) {
#pragma unroll
            for (int it = 0; it < 6; ++it) {
                int i = tid + 256 * it;
                int r = i / 12, q2 = i % 12;
                float4 v = *(float4*)(ob + r * 52 + 4 * q2);
                *(float4*)(out + (rowbase + r) * CACT + 4 * q2) = v;
            }
        } else {
#pragma unroll
            for (int it = 0; it < 2; ++it) {
                int i = tid + 256 * it;
                int r = i >> 2, q2 = i & 3;
                float4 v = *(float4*)(ob + r * 52 + 4 * q2);
                *(float4*)(out + (rowbase + r) * CACT + 48 + 4 * q2) = v;
            }
            float* outT = out + (long)NROWS * CACT;
#pragma unroll
            for (int it = 0; it < 4; ++it) {
                int i = tid + 256 * it;
                int r = i >> 3, q2 = i & 7;
                float4 v = *(float4*)(ob + r * 52 + 16 + 4 * q2);
                *(float4*)(outT + (rowbase + r) * CTIME + 4 * q2) = v;
            }
        }
        __syncthreads();
        if (tid == 0) {
            __threadfence();
            atomicAdd(&g_done[b], 1);
        }
    } else {
        // ============ proto role: parallel G/M sims, then merge into out (verbatim R16) ============
        int pb = bx;
        int b = pb / 3, part = pb % 3;
        int clo = (part == 0) ? 4 : (part == 1) ? 36 : 68;
        int klo = (part == 2) ? 68 : 4;
        int khi = (part == 2) ? 100 : 68;
        int cbase = part * 32;

        float* Q   = sm + P_Q;
        float* Hn  = sm + P_HN;
        float* G   = sm + P_G;
        float* M   = sm + P_M;
        float* NUM = sm + P_SB;
        float* SIM = sm + P_N2;
        int* toks  = (int*)(sm + P_TOK);
        __shared__ int s_nev, s_first;
        __shared__ float s_n2[32];
        __shared__ int CL[CHUNK], TE[CHUNK];

        for (int i = tid; i < Tdim; i += 256) toks[i] = tokens[(long)b * Tdim + i];
        __syncthreads();

        float alpha = softplusf(part == 2 ? *ppt : *ppa);
        float scale = softplusf(part == 2 ? *pst : *psa) * softplusf(part == 2 ? *ptt : *pta);

        if (wid == 0) {
            int cnt = 0, first = 0x7fffffff;
            for (int ch = 0; ch < Tdim / 32; ++ch) {
                int t = ch * 32 + lane;
                bool isl = (toks[t] == LABEL_ID_);
                unsigned m = __ballot_sync(0xffffffffu, isl);
                int ntok = isl ? toks[(t + 1) & (Tdim - 1)] : 0;
                if (isl) {
                    int idx = cnt + __popc(m & ((1u << lane) - 1u));
                    g_evt[pb * Tdim + idx] = t;
                    g_evn[pb * Tdim + idx] = ntok;
                }
                unsigned m2 = __ballot_sync(0xffffffffu, isl && ntok >= klo && ntok < khi);
                if (lane == 0 && m2 && first == 0x7fffffff) {
                    int l2 = __ffs(m2) - 1;
                    first = cnt + __popc(m & ((1u << l2) - 1u));
                }
                cnt += __popc(m);
            }
            if (lane == 0) { s_nev = cnt; s_first = first; }
        } else {
            for (int c = wid - 1; c < 32; c += 7) {
                const float* e = E + (long)(clo + c) * Ddim;
                float v[8]; float ss = 0.f;
#pragma unroll
                for (int k = 0; k < 8; ++k) { v[k] = e[lane + 32 * k]; ss += v[k] * v[k]; }
#pragma unroll
                for (int o = 16; o > 0; o >>= 1) ss += __shfl_xor_sync(0xffffffffu, ss, o);
                float inv = alpha / fmaxf(sqrtf(ss), 1e-12f);
#pragma unroll
                for (int k = 0; k < 8; ++k) Q[c * 260 + lane + 32 * k] = v[k] * inv;
            }
            if (wid == 1 && lane < 32) s_n2[lane] = alpha * alpha;
        }
        __syncthreads();

        int nev = s_nev, first_sup = s_first;
        const float* hb = h + (long)b * Tdim * Ddim;

        for (int c0 = 0; c0 < nev; c0 += CHUNK) {
            int cl = min(CHUNK, nev - c0);

            if (tid < cl) {
                TE[tid] = g_evt[pb * Tdim + c0 + tid];
                CL[tid] = g_evn[pb * Tdim + c0 + tid] - clo;
            }
            __syncthreads();
            for (int r = wid; r < cl; r += 8) {
                const float* hr = hb + (long)TE[r] * Ddim;
                float v[8]; float ss = 0.f;
#pragma unroll
                for (int k = 0; k < 8; ++k) { v[k] = hr[lane + 32 * k]; ss += v[k] * v[k]; }
#pragma unroll
                for (int o = 16; o > 0; o >>= 1) ss += __shfl_xor_sync(0xffffffffu, ss, o);
                float inv = 1.0f / fmaxf(sqrtf(ss), 1e-12f);
#pragma unroll
                for (int k = 0; k < 8; ++k) Hn[r * 260 + lane + 32 * k] = v[k] * inv;
            }
            __syncthreads();

            int cc = tid >> 3, seg = tid & 7;
            {
                float qv[32];
#pragma unroll
                for (int k = 0; k < 32; ++k)
                    qv[k] = Q[cc * 260 + seg * 32 + ((k + 4 * seg) & 31)];
                for (int e = 0; e < cl; ++e) {
                    const float* he = Hn + e * 260 + seg * 32;
                    float p0 = 0.f, p1 = 0.f, p2 = 0.f, p3 = 0.f;
#pragma unroll
                    for (int k = 0; k < 32; k += 4) {
                        p0 += qv[k]     * he[(k + 4 * seg) & 31];
                        p1 += qv[k + 1] * he[(k + 1 + 4 * seg) & 31];
                        p2 += qv[k + 2] * he[(k + 2 + 4 * seg) & 31];
                        p3 += qv[k + 3] * he[(k + 3 + 4 * seg) & 31];
                    }
                    float s1 = (p0 + p1) + (p2 + p3);
                    s1 += __shfl_xor_sync(0xffffffffu, s1, 4);
                    s1 += __shfl_xor_sync(0xffffffffu, s1, 2);
                    s1 += __shfl_xor_sync(0xffffffffu, s1, 1);
                    if (seg == 0) M[e * 32 + cc] = s1;
                }
            }
            {
                float hv[32];
#pragma unroll
                for (int k = 0; k < 32; ++k)
                    hv[k] = (cc < cl) ? Hn[cc * 260 + seg * 32 + ((k + 4 * seg) & 31)] : 0.f;
                for (int e = 0; e < cl; ++e) {
                    const float* he = Hn + e * 260 + seg * 32;
                    float p0 = 0.f, p1 = 0.f, p2 = 0.f, p3 = 0.f;
#pragma unroll
                    for (int k = 0; k < 32; k += 4) {
                        p0 += hv[k]     * he[(k + 4 * seg) & 31];
                        p1 += hv[k + 1] * he[(k + 1 + 4 * seg) & 31];
                        p2 += hv[k + 2] * he[(k + 2 + 4 * seg) & 31];
                        p3 += hv[k + 3] * he[(k + 3 + 4 * seg) & 31];
                    }
                    float s1 = (p0 + p1) + (p2 + p3);
                    s1 += __shfl_xor_sync(0xffffffffu, s1, 4);
                    s1 += __shfl_xor_sync(0xffffffffu, s1, 2);
                    s1 += __shfl_xor_sync(0xffffffffu, s1, 1);
                    if (seg == 0 && cc < cl) G[e * 32 + cc] = s1;
                }
            }
            __syncthreads();

            for (int idx = tid; idx < cl * 32; idx += 256) {
                int e = idx >> 5, c = idx & 31;
                float num = M[e * 32 + c];
                for (int e2 = 0; e2 < e; ++e2)
                    if (CL[e2] == c) num += G[e * 32 + e2];
                NUM[e * 32 + c] = num;
            }
            __syncthreads();
            for (int idx = tid; idx < cl * 32; idx += 256) {
                int e = idx >> 5, c = idx & 31;
                float n2 = s_n2[c];
                for (int e2 = 0; e2 < e; ++e2)
                    if (CL[e2] == c) n2 += 2.f * NUM[e2 * 32 + c] + G[e2 * 32 + e2];
                float num = NUM[e * 32 + c];
                SIM[e * 32 + c] = (c0 + e > first_sup) ? scale * num * rsqrtf(n2) : 0.f;
            }
            __syncthreads();

            for (int idx = tid; idx < cl * 32; idx += 256) {
                int e = idx >> 5, c = idx & 31;
                g_scr[((long)b * Tdim + TE[e]) * 96 + cbase + c] = SIM[e * 32 + c];
            }
            if (c0 + CHUNK < nev) {
                if (tid < 32) {
                    int c = tid;
                    float n2 = s_n2[c];
                    for (int e = 0; e < cl; ++e)
                        if (CL[e] == c) n2 += 2.f * NUM[e * 32 + c] + G[e * 32 + e];
                    s_n2[c] = n2;
                }
                __syncthreads();
                for (int e = 0; e < cl; ++e) {
                    int c2 = CL[e];
                    if (c2 >= 0 && c2 < 32)
                        Q[c2 * 260 + tid] += Hn[e * 260 + tid];
                }
                __syncthreads();
            }
        }

        // ---- merge: wait for this batch's 32 gemm blocks, then add our slice ----
        __threadfence();
        if (tid == 0) {
            while (*(volatile int*)&g_done[b] < 32) __nanosleep(64);
            __threadfence();
        }
        __syncthreads();

        float* outT = out + (long)NROWS * CACT;
        for (int e = tid >> 5; e < nev; e += 8) {
            long row = (long)b * Tdim + g_evt[pb * Tdim + e];
            int c = lane;
            float v = __ldcg(&g_scr[row * 96 + cbase + c]);
            if (part < 2) out[row * CACT + cbase + c] += v;
            else          outT[row * CTIME + c] += v;
        }
    }
}

extern "C" void kernel_launch(void* const* d_in, const int* in_sizes, int n_in,
                              void* d_out, int out_size)
{
    cudaFuncSetAttribute(fat_kernel, cudaFuncAttributeMaxDynamicSharedMemorySize, SMEM_BYTES);

    reset_kernel<<<1, 32>>>();

    fat_kernel<<<24 + 256, 256, SMEM_BYTES>>>(
        (const int*)d_in[0], (const float*)d_in[1], (const float*)d_in[2],
        (const float*)d_in[3], (const float*)d_in[4],
        (const float*)d_in[5], (const float*)d_in[6],
        (const float*)d_in[7], (const float*)d_in[8],
        (const float*)d_in[9], (const float*)d_in[10],
        (const float*)d_in[11], (const float*)d_in[12],
        (const float*)d_in[13], (const float*)d_in[14],
        (float*)d_out);
}